// round 14
// baseline (speedup 1.0000x reference)
#include <cuda_runtime.h>
#include <cstdint>
#include <math.h>

#define B_  2
#define S_  2048
#define D_  1024
#define H_  16
#define DK_ 64
#define N_  (B_*S_)

// Scratch (device globals — no allocation allowed). All tf32-bit payloads.
__device__ uint32_t g_qt[N_*D_];
__device__ uint32_t g_kt[N_*D_];
__device__ uint32_t g_vt[N_*D_];
__device__ uint32_t g_wqt[D_*D_];
__device__ uint32_t g_wkt[D_*D_];
__device__ uint32_t g_wvt[D_*D_];
__device__ uint32_t g_wot[D_*D_];
__device__ uint32_t g_Qh[N_*D_];    // [B,H,S,DK] tf32
__device__ uint32_t g_Kh[N_*D_];
__device__ uint32_t g_Vh[N_*D_];
__device__ uint32_t g_ctx[N_*D_];   // [B,S,D] tf32

// ============================ helpers ======================================
__device__ __forceinline__ uint32_t f2tf32(float x) {
    uint32_t r;
    asm("cvt.rna.tf32.f32 %0, %1;" : "=r"(r) : "f"(x));
    return r;
}
__device__ __forceinline__ uint32_t smem_u32(const void* p) {
    uint32_t a;
    asm("{ .reg .u64 t; cvta.to.shared.u64 t, %1; cvt.u32.u64 %0, t; }"
        : "=r"(a) : "l"(p));
    return a;
}
__device__ __forceinline__ void cp16(uint32_t sdst, const void* gsrc) {
    asm volatile("cp.async.cg.shared.global [%0], [%1], 16;"
                 :: "r"(sdst), "l"(gsrc) : "memory");
}
#define CP_COMMIT() asm volatile("cp.async.commit_group;" ::: "memory")
#define CP_WAIT(n)  asm volatile("cp.async.wait_group %0;" :: "n"(n) : "memory")

__device__ __forceinline__ void mma_tf32(float c[4],
                                         uint32_t a0, uint32_t a1, uint32_t a2, uint32_t a3,
                                         uint32_t b0, uint32_t b1) {
    asm volatile(
        "mma.sync.aligned.m16n8k8.row.col.f32.tf32.tf32.f32 "
        "{%0,%1,%2,%3}, {%4,%5,%6,%7}, {%8,%9}, {%0,%1,%2,%3};"
        : "+f"(c[0]), "+f"(c[1]), "+f"(c[2]), "+f"(c[3])
        : "r"(a0), "r"(a1), "r"(a2), "r"(a3), "r"(b0), "r"(b1));
}

// ===========================================================================
// fp32 -> tf32 conversion, all 7 tensors in one launch.
// ===========================================================================
__global__ __launch_bounds__(256) void cvt_all_kernel(
    const float* __restrict__ q, const float* __restrict__ k, const float* __restrict__ v,
    const float* __restrict__ wq, const float* __restrict__ wk,
    const float* __restrict__ wv, const float* __restrict__ wo)
{
    const int y = blockIdx.y;
    const float* src;
    uint32_t* dst;
    switch (y) {
        case 0: src = q;  dst = g_qt;  break;
        case 1: src = k;  dst = g_kt;  break;
        case 2: src = v;  dst = g_vt;  break;
        case 3: src = wq; dst = g_wqt; break;
        case 4: src = wk; dst = g_wkt; break;
        case 5: src = wv; dst = g_wvt; break;
        default: src = wo; dst = g_wot; break;
    }
    if (y >= 3 && blockIdx.x >= 1024) return;
    const int i = (blockIdx.x * 256 + threadIdx.x) * 4;
    const float4 vv = *(const float4*)&src[i];
    uint4 t;
    t.x = f2tf32(vv.x); t.y = f2tf32(vv.y); t.z = f2tf32(vv.z); t.w = f2tf32(vv.w);
    *(uint4*)&dst[i] = t;
}

// ===========================================================================
// tf32 GEMM v2: 512 threads, 16 warps (4m x 4n), warp tile 32x32.
// cp.async 3-stage; CTA tile 128x128, K-chunk 32.
// acc = 32 regs/thread -> 2 CTAs/SM at 64-reg cap (8 warps/SMSP).
// QKV=true: blockIdx.z in {0,1,2} selects (q,k,v) triple, SPLIT layout out.
// ===========================================================================
#define AS_STRIDE 36
#define BS_STRIDE 136
#define AST_FLOATS (128 * AS_STRIDE)
#define BST_FLOATS (32 * BS_STRIDE)
#define STG_FLOATS (AST_FLOATS + BST_FLOATS)
#define GEMM_SMEM (3 * STG_FLOATS * 4)   // 107520 B

template<bool QKV>
__global__ __launch_bounds__(512, 2)
void gemm_cp_kernel(const uint32_t* __restrict__ A0, const uint32_t* __restrict__ B0,
                    const float* __restrict__ bias0, void* __restrict__ Y0)
{
    extern __shared__ uint32_t smu[];
    const uint32_t smem_base = smem_u32(smu);

    const uint32_t* A_;
    const uint32_t* Bm;
    const float* bias;
    void* Yv;
    if (QKV) {
        const int z = blockIdx.z;
        A_   = (z == 0) ? g_qt  : (z == 1) ? g_kt  : g_vt;
        Bm   = (z == 0) ? g_wqt : (z == 1) ? g_wkt : g_wvt;
        bias = (z == 0) ? bias0 : (z == 1) ? (const float*)B0 : (const float*)Y0;
        Yv   = (z == 0) ? (void*)g_Qh : (z == 1) ? (void*)g_Kh : (void*)g_Vh;
    } else {
        A_ = A0; Bm = B0; bias = bias0; Yv = Y0;
    }

    const int tid  = threadIdx.x;
    const int wid  = tid >> 5, lane = tid & 31;
    const int g    = lane >> 2, t4 = lane & 3;
    const int wm   = wid >> 2, wn = wid & 3;      // 4 x 4 warp grid
    const int rowBase = blockIdx.y * 128;
    const int colBase = blockIdx.x * 128;

    auto issue = [&](int ch, int stg) {
        const uint32_t abase = smem_base + (uint32_t)stg * (STG_FLOATS * 4);
        const uint32_t bbase = abase + AST_FLOATS * 4;
        #pragma unroll
        for (int j = 0; j < 2; j++) {
            const int slot = tid + 512 * j;       // 0..1023 float4 slots
            const int row = slot >> 3, f4 = slot & 7;
            cp16(abase + (row * AS_STRIDE + f4 * 4) * 4,
                 A_ + (size_t)(rowBase + row) * D_ + ch * 32 + f4 * 4);
            const int kr = slot >> 5, nq = slot & 31;
            cp16(bbase + (kr * BS_STRIDE + nq * 4) * 4,
                 Bm + (size_t)(ch * 32 + kr) * D_ + colBase + nq * 4);
        }
        CP_COMMIT();
    };

    float acc[2][4][4];
    #pragma unroll
    for (int mt = 0; mt < 2; mt++)
        #pragma unroll
        for (int nt = 0; nt < 4; nt++)
            #pragma unroll
            for (int r = 0; r < 4; r++) acc[mt][nt][r] = 0.f;

    issue(0, 0);
    issue(1, 1);

    for (int ch = 0; ch < 32; ch++) {
        CP_WAIT(1);
        __syncthreads();   // data visible + all warps done reading stage ch%3 from prev lap

        if (ch + 2 < 32) issue(ch + 2, (ch + 2) % 3);

        const uint32_t* A  = smu + (ch % 3) * STG_FLOATS;
        const uint32_t* Bv = A + AST_FLOATS;

        #pragma unroll
        for (int ks = 0; ks < 4; ks++) {
            const int k0 = ks * 8;
            uint32_t a[2][4];
            #pragma unroll
            for (int mt = 0; mt < 2; mt++) {
                const int m0 = wm * 32 + mt * 16;
                a[mt][0] = A[(m0 + g    ) * AS_STRIDE + k0 + t4    ];
                a[mt][1] = A[(m0 + g + 8) * AS_STRIDE + k0 + t4    ];
                a[mt][2] = A[(m0 + g    ) * AS_STRIDE + k0 + t4 + 4];
                a[mt][3] = A[(m0 + g + 8) * AS_STRIDE + k0 + t4 + 4];
            }
            #pragma unroll
            for (int nt = 0; nt < 4; nt++) {
                const int n0 = wn * 32 + nt * 8;
                const uint32_t b0 = Bv[(k0 + t4    ) * BS_STRIDE + n0 + g];
                const uint32_t b1 = Bv[(k0 + t4 + 4) * BS_STRIDE + n0 + g];
                #pragma unroll
                for (int mt = 0; mt < 2; mt++)
                    mma_tf32(acc[mt][nt], a[mt][0], a[mt][1], a[mt][2], a[mt][3], b0, b1);
            }
        }
    }

    #pragma unroll
    for (int mt = 0; mt < 2; mt++) {
        const int r0 = rowBase + wm * 32 + mt * 16 + g;
        #pragma unroll
        for (int nt = 0; nt < 4; nt++) {
            const int cb = colBase + wn * 32 + nt * 8 + t4 * 2;
            const float2 bb = *(const float2*)&bias[cb];
            float2 v0, v1;
            v0.x = acc[mt][nt][0] + bb.x; v0.y = acc[mt][nt][1] + bb.y;
            v1.x = acc[mt][nt][2] + bb.x; v1.y = acc[mt][nt][3] + bb.y;
            if (QKV) {
                uint32_t* Y = (uint32_t*)Yv;
                const int h = cb >> 6, dk = cb & (DK_-1);
                const int b0i = r0 >> 11, s0 = r0 & (S_-1);
                uint2 u0; u0.x = f2tf32(v0.x); u0.y = f2tf32(v0.y);
                *(uint2*)&Y[(((b0i*H_ + h)*S_) + s0)*DK_ + dk] = u0;
                const int r1 = r0 + 8;
                const int b1i = r1 >> 11, s1 = r1 & (S_-1);
                uint2 u1; u1.x = f2tf32(v1.x); u1.y = f2tf32(v1.y);
                *(uint2*)&Y[(((b1i*H_ + h)*S_) + s1)*DK_ + dk] = u1;
            } else {
                float* Y = (float*)Yv;
                *(float2*)&Y[(size_t)r0 * D_ + cb] = v0;
                *(float2*)&Y[(size_t)(r0 + 8) * D_ + cb] = v1;
            }
        }
    }
}

// ===========================================================================
// Causal flash attention v3 (unchanged from round 13): tf32 mma.sync,
// 2 CTAs/SM, Q in smem plane, phase-split single-buffer cp.async pipeline.
// smem: Qs[128][68] + Ks[64][68] + Vs[64][68] + Ps[128][68] = 104448 B.
// ===========================================================================
#define ATT_STRIDE 68
#define KV_FLOATS (64 * ATT_STRIDE)
#define Q_FLOATS  (128 * ATT_STRIDE)
#define ATT_SMEM ((2 * Q_FLOATS + 2 * KV_FLOATS) * 4)   // 104448

__global__ __launch_bounds__(256, 2)
void attn_mma_kernel(uint32_t* __restrict__ ctx)
{
    extern __shared__ uint32_t smw[];
    uint32_t* Qs = smw;                       // [128][68]
    uint32_t* Ks = smw + Q_FLOATS;            // [64][68]
    uint32_t* Vs = Ks + KV_FLOATS;            // [64][68]
    uint32_t* Ps = Vs + KV_FLOATS;            // [128][68]
    const uint32_t smem_base = smem_u32(smw);
    const uint32_t koff = smem_base + Q_FLOATS * 4;
    const uint32_t voff = koff + KV_FLOATS * 4;

    const int tid  = threadIdx.x;
    const int wid  = tid >> 5, lane = tid & 31;
    const int g    = lane >> 2, t4 = lane & 3;
    const int qt   = (int)gridDim.x - 1 - (int)blockIdx.x;   // heavy tiles first
    const int bh   = blockIdx.y;
    const int m0   = wid * 16;

    const uint32_t* Qg = g_Qh + (size_t)bh * (S_*DK_) + qt * 128 * DK_;
    const uint32_t* Kg = g_Kh + (size_t)bh * (S_*DK_);
    const uint32_t* Vg = g_Vh + (size_t)bh * (S_*DK_);

    // ---- prologue: one group = Q plane + K tile 0 ----
    #pragma unroll
    for (int j = 0; j < 8; j++) {
        const int slot = tid + 256 * j;            // 0..2047
        const int row = slot >> 4, cq = (slot & 15) * 4;
        cp16(smem_base + (row * ATT_STRIDE + cq) * 4,
             Qg + (size_t)row * DK_ + cq);
    }
    #pragma unroll
    for (int j = 0; j < 4; j++) {
        const int slot = tid + 256 * j;
        const int row = slot >> 4, cq = (slot & 15) * 4;
        cp16(koff + (row * ATT_STRIDE + cq) * 4,
             Kg + (size_t)row * DK_ + cq);
    }
    CP_COMMIT();

    float m[2] = { -1e30f, -1e30f };
    float l[2] = { 0.f, 0.f };
    float o[8][4];
    #pragma unroll
    for (int nt = 0; nt < 8; nt++)
        #pragma unroll
        for (int r = 0; r < 4; r++) o[nt][r] = 0.f;

    const int nk = 2 * qt + 2;
    const int rowg0 = qt * 128 + m0 + g;

    for (int kt = 0; kt < nk; kt++) {
        const bool has_next = (kt + 1 < nk);

        // ---- top: K(kt) (and Q on iter 0) complete ----
        CP_WAIT(0);
        __syncthreads();

        // ---- issue V(kt): lands during QK + softmax ----
        #pragma unroll
        for (int j = 0; j < 4; j++) {
            const int slot = tid + 256 * j;
            const int row = slot >> 4, cq = (slot & 15) * 4;
            cp16(voff + (row * ATT_STRIDE + cq) * 4,
                 Vg + (size_t)(kt * 64 + row) * DK_ + cq);
        }
        CP_COMMIT();

        // ---- S = Q K^T ----
        float sc[8][4];
        #pragma unroll
        for (int nt = 0; nt < 8; nt++)
            #pragma unroll
            for (int r = 0; r < 4; r++) sc[nt][r] = 0.f;

        #pragma unroll
        for (int ks = 0; ks < 8; ks++) {
            const int k0 = ks * 8;
            const uint32_t a0 = Qs[(m0 + g    ) * ATT_STRIDE + k0 + t4    ];
            const uint32_t a1 = Qs[(m0 + g + 8) * ATT_STRIDE + k0 + t4    ];
            const uint32_t a2 = Qs[(m0 + g    ) * ATT_STRIDE + k0 + t4 + 4];
            const uint32_t a3 = Qs[(m0 + g + 8) * ATT_STRIDE + k0 + t4 + 4];
            #pragma unroll
            for (int nt = 0; nt < 8; nt++) {
                const uint32_t b0 = Ks[(nt*8 + g) * ATT_STRIDE + k0 + t4    ];
                const uint32_t b1 = Ks[(nt*8 + g) * ATT_STRIDE + k0 + t4 + 4];
                mma_tf32(sc[nt], a0, a1, a2, a3, b0, b1);
            }
        }

        __syncthreads();   // all warps done reading Ks

        // ---- issue K(kt+1): hides under softmax + PV ----
        if (has_next) {
            #pragma unroll
            for (int j = 0; j < 4; j++) {
                const int slot = tid + 256 * j;
                const int row = slot >> 4, cq = (slot & 15) * 4;
                cp16(koff + (row * ATT_STRIDE + cq) * 4,
                     Kg + (size_t)((kt + 1) * 64 + row) * DK_ + cq);
            }
            CP_COMMIT();
        }

        // ---- scale + causal mask ----
        const bool need_mask = (kt >= 2 * qt);
        const int colBase = kt * 64;
        #pragma unroll
        for (int nt = 0; nt < 8; nt++) {
            #pragma unroll
            for (int r = 0; r < 4; r++) sc[nt][r] *= 0.125f;
            if (need_mask) {
                const int c0 = colBase + nt*8 + 2*t4;
                if (c0     > rowg0    ) sc[nt][0] = -1e30f;
                if (c0 + 1 > rowg0    ) sc[nt][1] = -1e30f;
                if (c0     > rowg0 + 8) sc[nt][2] = -1e30f;
                if (c0 + 1 > rowg0 + 8) sc[nt][3] = -1e30f;
            }
        }

        // ---- online softmax ----
        #pragma unroll
        for (int r = 0; r < 2; r++) {
            float rm = -1e30f;
            #pragma unroll
            for (int nt = 0; nt < 8; nt++)
                rm = fmaxf(rm, fmaxf(sc[nt][2*r], sc[nt][2*r+1]));
            rm = fmaxf(rm, __shfl_xor_sync(0xffffffffu, rm, 1));
            rm = fmaxf(rm, __shfl_xor_sync(0xffffffffu, rm, 2));
            const float mn = fmaxf(m[r], rm);
            const float alpha = __expf(m[r] - mn);
            m[r] = mn;
            float rs = 0.f;
            #pragma unroll
            for (int nt = 0; nt < 8; nt++) {
                const float p0 = __expf(sc[nt][2*r  ] - mn);
                const float p1 = __expf(sc[nt][2*r+1] - mn);
                sc[nt][2*r] = p0; sc[nt][2*r+1] = p1;
                rs += p0 + p1;
            }
            rs += __shfl_xor_sync(0xffffffffu, rs, 1);
            rs += __shfl_xor_sync(0xffffffffu, rs, 2);
            l[r] = l[r] * alpha + rs;
            #pragma unroll
            for (int nt = 0; nt < 8; nt++) {
                o[nt][2*r] *= alpha; o[nt][2*r+1] *= alpha;
            }
        }

        // ---- P -> Ps (warp-private rows) ----
        __syncwarp();
        #pragma unroll
        for (int nt = 0; nt < 8; nt++) {
            uint2 w0, w1;
            w0.x = f2tf32(sc[nt][0]); w0.y = f2tf32(sc[nt][1]);
            w1.x = f2tf32(sc[nt][2]); w1.y = f2tf32(sc[nt][3]);
            *(uint2*)&Ps[(m0 + g    ) * ATT_STRIDE + nt*8 + 2*t4] = w0;
            *(uint2*)&Ps[(m0 + g + 8) * ATT_STRIDE + nt*8 + 2*t4] = w1;
        }
        __syncwarp();

        // ---- pre-PV: V(kt) complete (K(kt+1) may remain in flight) ----
        if (has_next) { CP_WAIT(1); }
        else          { CP_WAIT(0); }
        __syncthreads();

        // ---- O += P V ----
        #pragma unroll
        for (int ks = 0; ks < 8; ks++) {
            const int k0 = ks * 8;
            const uint32_t a0 = Ps[(m0 + g    ) * ATT_STRIDE + k0 + t4    ];
            const uint32_t a1 = Ps[(m0 + g + 8) * ATT_STRIDE + k0 + t4    ];
            const uint32_t a2 = Ps[(m0 + g    ) * ATT_STRIDE + k0 + t4 + 4];
            const uint32_t a3 = Ps[(m0 + g + 8) * ATT_STRIDE + k0 + t4 + 4];
            #pragma unroll
            for (int nt = 0; nt < 8; nt++) {
                const uint32_t b0 = Vs[(k0 + t4    ) * ATT_STRIDE + nt*8 + g];
                const uint32_t b1 = Vs[(k0 + t4 + 4) * ATT_STRIDE + nt*8 + g];
                mma_tf32(o[nt], a0, a1, a2, a3, b0, b1);
            }
        }
        // next iteration's top barrier protects Vs/Ps before refill
    }

    // ---- epilogue: normalize, store ctx tf32 bits [B,S,D] ----
    const int b = bh >> 4, h = bh & 15;
    #pragma unroll
    for (int r = 0; r < 2; r++) {
        const float inv = 1.0f / l[r];
        const int srow = qt*128 + m0 + g + (r ? 8 : 0);
        uint32_t* dst = &ctx[((size_t)b * S_ + srow) * D_ + h * DK_];
        #pragma unroll
        for (int nt = 0; nt < 8; nt++) {
            uint2 v;
            v.x = f2tf32(o[nt][2*r  ] * inv);
            v.y = f2tf32(o[nt][2*r+1] * inv);
            *(uint2*)&dst[nt*8 + 2*t4] = v;
        }
    }
}

// ---------------------------------------------------------------------------
extern "C" void kernel_launch(void* const* d_in, const int* in_sizes, int n_in,
                              void* d_out, int out_size)
{
    const float* q   = (const float*)d_in[0];
    const float* k   = (const float*)d_in[1];
    const float* v   = (const float*)d_in[2];
    // d_in[3] = mask (causal, applied analytically)
    const float* w_q = (const float*)d_in[4];
    const float* b_q = (const float*)d_in[5];
    const float* w_k = (const float*)d_in[6];
    const float* b_k = (const float*)d_in[7];
    const float* w_v = (const float*)d_in[8];
    const float* b_v = (const float*)d_in[9];
    const float* w_o = (const float*)d_in[10];
    const float* b_o = (const float*)d_in[11];
    float* out = (float*)d_out;

    uint32_t *wot, *ctx;
    cudaGetSymbolAddress((void**)&wot, g_wot);
    cudaGetSymbolAddress((void**)&ctx, g_ctx);

    cudaFuncSetAttribute(gemm_cp_kernel<true>,
                         cudaFuncAttributeMaxDynamicSharedMemorySize, GEMM_SMEM);
    cudaFuncSetAttribute(gemm_cp_kernel<false>,
                         cudaFuncAttributeMaxDynamicSharedMemorySize, GEMM_SMEM);
    cudaFuncSetAttribute(attn_mma_kernel,
                         cudaFuncAttributeMaxDynamicSharedMemorySize, ATT_SMEM);

    cvt_all_kernel<<<dim3(N_*D_/1024, 7), 256>>>(q, k, v, w_q, w_k, w_v, w_o);

    // merged QKV projections: z selects stream; biases smuggled via B0/bias0/Y0
    gemm_cp_kernel<true ><<<dim3(D_/128, N_/128, 3), 512, GEMM_SMEM>>>(
        nullptr, (const uint32_t*)b_k, b_q, (void*)b_v);

    attn_mma_kernel<<<dim3(S_/128, B_*H_), 256, ATT_SMEM>>>(ctx);

    gemm_cp_kernel<false><<<dim3(D_/128, N_/128), 512, GEMM_SMEM>>>(ctx, wot, b_o, out);
}

// round 16
// speedup vs baseline: 1.0213x; 1.0213x over previous
#include <cuda_runtime.h>
#include <cstdint>
#include <math.h>

#define B_  2
#define S_  2048
#define D_  1024
#define H_  16
#define DK_ 64
#define N_  (B_*S_)

// Scratch (device globals — no allocation allowed). All tf32-bit payloads.
__device__ uint32_t g_qt[N_*D_];
__device__ uint32_t g_kt[N_*D_];
__device__ uint32_t g_vt[N_*D_];
__device__ uint32_t g_wqt[D_*D_];
__device__ uint32_t g_wkt[D_*D_];
__device__ uint32_t g_wvt[D_*D_];
__device__ uint32_t g_wot[D_*D_];
__device__ uint32_t g_Qh[N_*D_];    // [B,H,S,DK] tf32
__device__ uint32_t g_Kh[N_*D_];
__device__ uint32_t g_Vh[N_*D_];
__device__ uint32_t g_ctx[N_*D_];   // [B,S,D] tf32

// ============================ helpers ======================================
__device__ __forceinline__ uint32_t f2tf32(float x) {
    uint32_t r;
    asm("cvt.rna.tf32.f32 %0, %1;" : "=r"(r) : "f"(x));
    return r;
}
__device__ __forceinline__ uint32_t smem_u32(const void* p) {
    uint32_t a;
    asm("{ .reg .u64 t; cvta.to.shared.u64 t, %1; cvt.u32.u64 %0, t; }"
        : "=r"(a) : "l"(p));
    return a;
}
__device__ __forceinline__ void cp16(uint32_t sdst, const void* gsrc) {
    asm volatile("cp.async.cg.shared.global [%0], [%1], 16;"
                 :: "r"(sdst), "l"(gsrc) : "memory");
}
#define CP_COMMIT() asm volatile("cp.async.commit_group;" ::: "memory")
#define CP_WAIT(n)  asm volatile("cp.async.wait_group %0;" :: "n"(n) : "memory")

__device__ __forceinline__ void mma_tf32(float c[4],
                                         uint32_t a0, uint32_t a1, uint32_t a2, uint32_t a3,
                                         uint32_t b0, uint32_t b1) {
    asm volatile(
        "mma.sync.aligned.m16n8k8.row.col.f32.tf32.tf32.f32 "
        "{%0,%1,%2,%3}, {%4,%5,%6,%7}, {%8,%9}, {%0,%1,%2,%3};"
        : "+f"(c[0]), "+f"(c[1]), "+f"(c[2]), "+f"(c[3])
        : "r"(a0), "r"(a1), "r"(a2), "r"(a3), "r"(b0), "r"(b1));
}

// ===========================================================================
// fp32 -> tf32 conversion, all 7 tensors in one launch.
// ===========================================================================
__global__ __launch_bounds__(256) void cvt_all_kernel(
    const float* __restrict__ q, const float* __restrict__ k, const float* __restrict__ v,
    const float* __restrict__ wq, const float* __restrict__ wk,
    const float* __restrict__ wv, const float* __restrict__ wo)
{
    const int y = blockIdx.y;
    const float* src;
    uint32_t* dst;
    switch (y) {
        case 0: src = q;  dst = g_qt;  break;
        case 1: src = k;  dst = g_kt;  break;
        case 2: src = v;  dst = g_vt;  break;
        case 3: src = wq; dst = g_wqt; break;
        case 4: src = wk; dst = g_wkt; break;
        case 5: src = wv; dst = g_wvt; break;
        default: src = wo; dst = g_wot; break;
    }
    if (y >= 3 && blockIdx.x >= 1024) return;
    const int i = (blockIdx.x * 256 + threadIdx.x) * 4;
    const float4 vv = *(const float4*)&src[i];
    uint4 t;
    t.x = f2tf32(vv.x); t.y = f2tf32(vv.y); t.z = f2tf32(vv.z); t.w = f2tf32(vv.w);
    *(uint4*)&dst[i] = t;
}

// ===========================================================================
// tf32 GEMM (r13 shape + fragment double-buffering):
// 256 threads, 8 warps (2m x 4n), warp tile 64x32, cp.async 3-stage,
// CTA tile 128x128, K-chunk 32. Frags for ks+1 load during MMAs of ks.
// QKV=true: blockIdx.z in {0,1,2} selects (q,k,v) triple, SPLIT layout out.
// ===========================================================================
#define AS_STRIDE 36
#define BS_STRIDE 136
#define AST_FLOATS (128 * AS_STRIDE)
#define BST_FLOATS (32 * BS_STRIDE)
#define STG_FLOATS (AST_FLOATS + BST_FLOATS)
#define GEMM_SMEM (3 * STG_FLOATS * 4)   // 107520 B

template<bool QKV>
__global__ __launch_bounds__(256, 2)
void gemm_cp_kernel(const uint32_t* __restrict__ A0, const uint32_t* __restrict__ B0,
                    const float* __restrict__ bias0, void* __restrict__ Y0)
{
    extern __shared__ uint32_t smu[];
    const uint32_t smem_base = smem_u32(smu);

    const uint32_t* A_;
    const uint32_t* Bm;
    const float* bias;
    void* Yv;
    if (QKV) {
        const int z = blockIdx.z;
        A_   = (z == 0) ? g_qt  : (z == 1) ? g_kt  : g_vt;
        Bm   = (z == 0) ? g_wqt : (z == 1) ? g_wkt : g_wvt;
        bias = (z == 0) ? bias0 : (z == 1) ? (const float*)B0 : (const float*)Y0;
        Yv   = (z == 0) ? (void*)g_Qh : (z == 1) ? (void*)g_Kh : (void*)g_Vh;
    } else {
        A_ = A0; Bm = B0; bias = bias0; Yv = Y0;
    }

    const int tid  = threadIdx.x;
    const int wid  = tid >> 5, lane = tid & 31;
    const int g    = lane >> 2, t4 = lane & 3;
    const int wm   = wid >> 2, wn = wid & 3;
    const int rowBase = blockIdx.y * 128;
    const int colBase = blockIdx.x * 128;

    auto issue = [&](int ch, int stg) {
        const uint32_t abase = smem_base + (uint32_t)stg * (STG_FLOATS * 4);
        const uint32_t bbase = abase + AST_FLOATS * 4;
        #pragma unroll
        for (int j = 0; j < 4; j++) {
            const int slot = tid + 256 * j;
            const int row = slot >> 3, f4 = slot & 7;
            cp16(abase + (row * AS_STRIDE + f4 * 4) * 4,
                 A_ + (size_t)(rowBase + row) * D_ + ch * 32 + f4 * 4);
            const int kr = slot >> 5, nq = slot & 31;
            cp16(bbase + (kr * BS_STRIDE + nq * 4) * 4,
                 Bm + (size_t)(ch * 32 + kr) * D_ + colBase + nq * 4);
        }
        CP_COMMIT();
    };

    float acc[4][4][4];
    #pragma unroll
    for (int mt = 0; mt < 4; mt++)
        #pragma unroll
        for (int nt = 0; nt < 4; nt++)
            #pragma unroll
            for (int r = 0; r < 4; r++) acc[mt][nt][r] = 0.f;

    issue(0, 0);
    issue(1, 1);

    const int am0 = wm * 64;
    const int bn0 = wn * 32;

    for (int ch = 0; ch < 32; ch++) {
        CP_WAIT(1);
        __syncthreads();   // stage data visible; all warps done with stage ch%3 prev lap

        if (ch + 2 < 32) issue(ch + 2, (ch + 2) % 3);

        const uint32_t* A  = smu + (ch % 3) * STG_FLOATS;
        const uint32_t* Bv = A + AST_FLOATS;

        uint32_t a[2][4][4], b[2][4][2];

        // load frags for ks=0
        #pragma unroll
        for (int mt = 0; mt < 4; mt++) {
            const int m0 = am0 + mt * 16;
            a[0][mt][0] = A[(m0 + g    ) * AS_STRIDE + t4    ];
            a[0][mt][1] = A[(m0 + g + 8) * AS_STRIDE + t4    ];
            a[0][mt][2] = A[(m0 + g    ) * AS_STRIDE + t4 + 4];
            a[0][mt][3] = A[(m0 + g + 8) * AS_STRIDE + t4 + 4];
        }
        #pragma unroll
        for (int nt = 0; nt < 4; nt++) {
            b[0][nt][0] = Bv[(t4    ) * BS_STRIDE + bn0 + nt * 8 + g];
            b[0][nt][1] = Bv[(t4 + 4) * BS_STRIDE + bn0 + nt * 8 + g];
        }

        #pragma unroll
        for (int ks = 0; ks < 4; ks++) {
            const int cur = ks & 1, nxt = cur ^ 1;
            if (ks < 3) {
                const int k0 = (ks + 1) * 8;
                #pragma unroll
                for (int mt = 0; mt < 4; mt++) {
                    const int m0 = am0 + mt * 16;
                    a[nxt][mt][0] = A[(m0 + g    ) * AS_STRIDE + k0 + t4    ];
                    a[nxt][mt][1] = A[(m0 + g + 8) * AS_STRIDE + k0 + t4    ];
                    a[nxt][mt][2] = A[(m0 + g    ) * AS_STRIDE + k0 + t4 + 4];
                    a[nxt][mt][3] = A[(m0 + g + 8) * AS_STRIDE + k0 + t4 + 4];
                }
                #pragma unroll
                for (int nt = 0; nt < 4; nt++) {
                    b[nxt][nt][0] = Bv[(k0 + t4    ) * BS_STRIDE + bn0 + nt * 8 + g];
                    b[nxt][nt][1] = Bv[(k0 + t4 + 4) * BS_STRIDE + bn0 + nt * 8 + g];
                }
            }
            #pragma unroll
            for (int nt = 0; nt < 4; nt++)
                #pragma unroll
                for (int mt = 0; mt < 4; mt++)
                    mma_tf32(acc[mt][nt],
                             a[cur][mt][0], a[cur][mt][1], a[cur][mt][2], a[cur][mt][3],
                             b[cur][nt][0], b[cur][nt][1]);
        }
    }

    #pragma unroll
    for (int mt = 0; mt < 4; mt++) {
        const int r0 = rowBase + am0 + mt * 16 + g;
        #pragma unroll
        for (int nt = 0; nt < 4; nt++) {
            const int cb = colBase + bn0 + nt * 8 + t4 * 2;
            const float2 bb = *(const float2*)&bias[cb];
            float2 v0, v1;
            v0.x = acc[mt][nt][0] + bb.x; v0.y = acc[mt][nt][1] + bb.y;
            v1.x = acc[mt][nt][2] + bb.x; v1.y = acc[mt][nt][3] + bb.y;
            if (QKV) {
                uint32_t* Y = (uint32_t*)Yv;
                const int h = cb >> 6, dk = cb & (DK_-1);
                const int b0i = r0 >> 11, s0 = r0 & (S_-1);
                uint2 u0; u0.x = f2tf32(v0.x); u0.y = f2tf32(v0.y);
                *(uint2*)&Y[(((b0i*H_ + h)*S_) + s0)*DK_ + dk] = u0;
                const int r1 = r0 + 8;
                const int b1i = r1 >> 11, s1 = r1 & (S_-1);
                uint2 u1; u1.x = f2tf32(v1.x); u1.y = f2tf32(v1.y);
                *(uint2*)&Y[(((b1i*H_ + h)*S_) + s1)*DK_ + dk] = u1;
            } else {
                float* Y = (float*)Yv;
                *(float2*)&Y[(size_t)r0 * D_ + cb] = v0;
                *(float2*)&Y[(size_t)(r0 + 8) * D_ + cb] = v1;
            }
        }
    }
}

// ===========================================================================
// Causal flash attention v3b: tf32 mma.sync, 2 CTAs/SM, 2 barriers/iter.
// Br=128, Bc=64, 8 warps. Q in smem plane; single K and V buffers.
// Pipeline per iter:
//   top:   WAIT(0) -> K(kt) ready; sync; issue V(kt)
//   QK reads Ks; softmax; Ps bounce (warp-private)
//   prePV: WAIT(0) -> V(kt) ready; sync (also: all QK reads done);
//          issue K(kt+1); PV reads Vs/Ps
// smem: Qs[128][68] + Ks[64][68] + Vs[64][68] + Ps[128][68] = 104448 B.
// ===========================================================================
#define ATT_STRIDE 68
#define KV_FLOATS (64 * ATT_STRIDE)
#define Q_FLOATS  (128 * ATT_STRIDE)
#define ATT_SMEM ((2 * Q_FLOATS + 2 * KV_FLOATS) * 4)   // 104448

__global__ __launch_bounds__(256, 2)
void attn_mma_kernel(uint32_t* __restrict__ ctx)
{
    extern __shared__ uint32_t smw[];
    uint32_t* Qs = smw;                       // [128][68]
    uint32_t* Ks = smw + Q_FLOATS;            // [64][68]
    uint32_t* Vs = Ks + KV_FLOATS;            // [64][68]
    uint32_t* Ps = Vs + KV_FLOATS;            // [128][68]
    const uint32_t smem_base = smem_u32(smw);
    const uint32_t koff = smem_base + Q_FLOATS * 4;
    const uint32_t voff = koff + KV_FLOATS * 4;

    const int tid  = threadIdx.x;
    const int wid  = tid >> 5, lane = tid & 31;
    const int g    = lane >> 2, t4 = lane & 3;
    const int qt   = (int)gridDim.x - 1 - (int)blockIdx.x;   // heavy tiles first
    const int bh   = blockIdx.y;
    const int m0   = wid * 16;

    const uint32_t* Qg = g_Qh + (size_t)bh * (S_*DK_) + qt * 128 * DK_;
    const uint32_t* Kg = g_Kh + (size_t)bh * (S_*DK_);
    const uint32_t* Vg = g_Vh + (size_t)bh * (S_*DK_);

    // ---- prologue: one group = Q plane + K tile 0 ----
    #pragma unroll
    for (int j = 0; j < 8; j++) {
        const int slot = tid + 256 * j;            // 0..2047
        const int row = slot >> 4, cq = (slot & 15) * 4;
        cp16(smem_base + (row * ATT_STRIDE + cq) * 4,
             Qg + (size_t)row * DK_ + cq);
    }
    #pragma unroll
    for (int j = 0; j < 4; j++) {
        const int slot = tid + 256 * j;
        const int row = slot >> 4, cq = (slot & 15) * 4;
        cp16(koff + (row * ATT_STRIDE + cq) * 4,
             Kg + (size_t)row * DK_ + cq);
    }
    CP_COMMIT();

    float m[2] = { -1e30f, -1e30f };
    float l[2] = { 0.f, 0.f };
    float o[8][4];
    #pragma unroll
    for (int nt = 0; nt < 8; nt++)
        #pragma unroll
        for (int r = 0; r < 4; r++) o[nt][r] = 0.f;

    const int nk = 2 * qt + 2;
    const int rowg0 = qt * 128 + m0 + g;

    for (int kt = 0; kt < nk; kt++) {
        const bool has_next = (kt + 1 < nk);

        // ---- top: K(kt) (and Q on iter 0) complete; nothing else in flight ----
        CP_WAIT(0);
        __syncthreads();   // K visible; prev iter's Vs/Ps reads done

        // ---- issue V(kt): lands during QK + softmax ----
        #pragma unroll
        for (int j = 0; j < 4; j++) {
            const int slot = tid + 256 * j;
            const int row = slot >> 4, cq = (slot & 15) * 4;
            cp16(voff + (row * ATT_STRIDE + cq) * 4,
                 Vg + (size_t)(kt * 64 + row) * DK_ + cq);
        }
        CP_COMMIT();

        // ---- S = Q K^T ----
        float sc[8][4];
        #pragma unroll
        for (int nt = 0; nt < 8; nt++)
            #pragma unroll
            for (int r = 0; r < 4; r++) sc[nt][r] = 0.f;

        #pragma unroll
        for (int ks = 0; ks < 8; ks++) {
            const int k0 = ks * 8;
            const uint32_t a0 = Qs[(m0 + g    ) * ATT_STRIDE + k0 + t4    ];
            const uint32_t a1 = Qs[(m0 + g + 8) * ATT_STRIDE + k0 + t4    ];
            const uint32_t a2 = Qs[(m0 + g    ) * ATT_STRIDE + k0 + t4 + 4];
            const uint32_t a3 = Qs[(m0 + g + 8) * ATT_STRIDE + k0 + t4 + 4];
            #pragma unroll
            for (int nt = 0; nt < 8; nt++) {
                const uint32_t b0 = Ks[(nt*8 + g) * ATT_STRIDE + k0 + t4    ];
                const uint32_t b1 = Ks[(nt*8 + g) * ATT_STRIDE + k0 + t4 + 4];
                mma_tf32(sc[nt], a0, a1, a2, a3, b0, b1);
            }
        }

        // ---- scale + causal mask ----
        const bool need_mask = (kt >= 2 * qt);
        const int colBase = kt * 64;
        #pragma unroll
        for (int nt = 0; nt < 8; nt++) {
            #pragma unroll
            for (int r = 0; r < 4; r++) sc[nt][r] *= 0.125f;
            if (need_mask) {
                const int c0 = colBase + nt*8 + 2*t4;
                if (c0     > rowg0    ) sc[nt][0] = -1e30f;
                if (c0 + 1 > rowg0    ) sc[nt][1] = -1e30f;
                if (c0     > rowg0 + 8) sc[nt][2] = -1e30f;
                if (c0 + 1 > rowg0 + 8) sc[nt][3] = -1e30f;
            }
        }

        // ---- online softmax ----
        #pragma unroll
        for (int r = 0; r < 2; r++) {
            float rm = -1e30f;
            #pragma unroll
            for (int nt = 0; nt < 8; nt++)
                rm = fmaxf(rm, fmaxf(sc[nt][2*r], sc[nt][2*r+1]));
            rm = fmaxf(rm, __shfl_xor_sync(0xffffffffu, rm, 1));
            rm = fmaxf(rm, __shfl_xor_sync(0xffffffffu, rm, 2));
            const float mn = fmaxf(m[r], rm);
            const float alpha = __expf(m[r] - mn);
            m[r] = mn;
            float rs = 0.f;
            #pragma unroll
            for (int nt = 0; nt < 8; nt++) {
                const float p0 = __expf(sc[nt][2*r  ] - mn);
                const float p1 = __expf(sc[nt][2*r+1] - mn);
                sc[nt][2*r] = p0; sc[nt][2*r+1] = p1;
                rs += p0 + p1;
            }
            rs += __shfl_xor_sync(0xffffffffu, rs, 1);
            rs += __shfl_xor_sync(0xffffffffu, rs, 2);
            l[r] = l[r] * alpha + rs;
            #pragma unroll
            for (int nt = 0; nt < 8; nt++) {
                o[nt][2*r] *= alpha; o[nt][2*r+1] *= alpha;
            }
        }

        // ---- P -> Ps (warp-private rows) ----
        __syncwarp();
        #pragma unroll
        for (int nt = 0; nt < 8; nt++) {
            uint2 w0, w1;
            w0.x = f2tf32(sc[nt][0]); w0.y = f2tf32(sc[nt][1]);
            w1.x = f2tf32(sc[nt][2]); w1.y = f2tf32(sc[nt][3]);
            *(uint2*)&Ps[(m0 + g    ) * ATT_STRIDE + nt*8 + 2*t4] = w0;
            *(uint2*)&Ps[(m0 + g + 8) * ATT_STRIDE + nt*8 + 2*t4] = w1;
        }
        __syncwarp();

        // ---- pre-PV: V(kt) complete; barrier also closes all QK reads ----
        CP_WAIT(0);
        __syncthreads();

        // ---- issue K(kt+1): overlaps PV; completes by next top WAIT(0) ----
        if (has_next) {
            #pragma unroll
            for (int j = 0; j < 4; j++) {
                const int slot = tid + 256 * j;
                const int row = slot >> 4, cq = (slot & 15) * 4;
                cp16(koff + (row * ATT_STRIDE + cq) * 4,
                     Kg + (size_t)((kt + 1) * 64 + row) * DK_ + cq);
            }
            CP_COMMIT();
        }

        // ---- O += P V ----
        #pragma unroll
        for (int ks = 0; ks < 8; ks++) {
            const int k0 = ks * 8;
            const uint32_t a0 = Ps[(m0 + g    ) * ATT_STRIDE + k0 + t4    ];
            const uint32_t a1 = Ps[(m0 + g + 8) * ATT_STRIDE + k0 + t4    ];
            const uint32_t a2 = Ps[(m0 + g    ) * ATT_STRIDE + k0 + t4 + 4];
            const uint32_t a3 = Ps[(m0 + g + 8) * ATT_STRIDE + k0 + t4 + 4];
            #pragma unroll
            for (int nt = 0; nt < 8; nt++) {
                const uint32_t b0 = Vs[(k0 + t4    ) * ATT_STRIDE + nt*8 + g];
                const uint32_t b1 = Vs[(k0 + t4 + 4) * ATT_STRIDE + nt*8 + g];
                mma_tf32(o[nt], a0, a1, a2, a3, b0, b1);
            }
        }
        // next iteration's top barrier protects Vs/Ps before refill
    }

    // ---- epilogue: normalize, store ctx tf32 bits [B,S,D] ----
    const int b = bh >> 4, h = bh & 15;
    #pragma unroll
    for (int r = 0; r < 2; r++) {
        const float inv = 1.0f / l[r];
        const int srow = qt*128 + m0 + g + (r ? 8 : 0);
        uint32_t* dst = &ctx[((size_t)b * S_ + srow) * D_ + h * DK_];
        #pragma unroll
        for (int nt = 0; nt < 8; nt++) {
            uint2 v;
            v.x = f2tf32(o[nt][2*r  ] * inv);
            v.y = f2tf32(o[nt][2*r+1] * inv);
            *(uint2*)&dst[nt*8 + 2*t4] = v;
        }
    }
}

// ---------------------------------------------------------------------------
extern "C" void kernel_launch(void* const* d_in, const int* in_sizes, int n_in,
                              void* d_out, int out_size)
{
    const float* q   = (const float*)d_in[0];
    const float* k   = (const float*)d_in[1];
    const float* v   = (const float*)d_in[2];
    // d_in[3] = mask (causal, applied analytically)
    const float* w_q = (const float*)d_in[4];
    const float* b_q = (const float*)d_in[5];
    const float* w_k = (const float*)d_in[6];
    const float* b_k = (const float*)d_in[7];
    const float* w_v = (const float*)d_in[8];
    const float* b_v = (const float*)d_in[9];
    const float* w_o = (const float*)d_in[10];
    const float* b_o = (const float*)d_in[11];
    float* out = (float*)d_out;

    uint32_t *wot, *ctx;
    cudaGetSymbolAddress((void**)&wot, g_wot);
    cudaGetSymbolAddress((void**)&ctx, g_ctx);

    cudaFuncSetAttribute(gemm_cp_kernel<true>,
                         cudaFuncAttributeMaxDynamicSharedMemorySize, GEMM_SMEM);
    cudaFuncSetAttribute(gemm_cp_kernel<false>,
                         cudaFuncAttributeMaxDynamicSharedMemorySize, GEMM_SMEM);
    cudaFuncSetAttribute(attn_mma_kernel,
                         cudaFuncAttributeMaxDynamicSharedMemorySize, ATT_SMEM);

    cvt_all_kernel<<<dim3(N_*D_/1024, 7), 256>>>(q, k, v, w_q, w_k, w_v, w_o);

    // merged QKV projections: z selects stream; biases smuggled via B0/bias0/Y0
    gemm_cp_kernel<true ><<<dim3(D_/128, N_/128, 3), 256, GEMM_SMEM>>>(
        nullptr, (const uint32_t*)b_k, b_q, (void*)b_v);

    attn_mma_kernel<<<dim3(S_/128, B_*H_), 256, ATT_SMEM>>>(ctx);

    gemm_cp_kernel<false><<<dim3(D_/128, N_/128), 256, GEMM_SMEM>>>(ctx, wot, b_o, out);
}

// round 17
// speedup vs baseline: 1.0561x; 1.0341x over previous
#include <cuda_runtime.h>
#include <cstdint>
#include <math.h>

#define B_  2
#define S_  2048
#define D_  1024
#define H_  16
#define DK_ 64
#define N_  (B_*S_)

// Scratch (device globals — no allocation allowed). All tf32-bit payloads.
__device__ uint32_t g_qt[N_*D_];
__device__ uint32_t g_kt[N_*D_];
__device__ uint32_t g_vt[N_*D_];
__device__ uint32_t g_wqt[D_*D_];
__device__ uint32_t g_wkt[D_*D_];
__device__ uint32_t g_wvt[D_*D_];
__device__ uint32_t g_wot[D_*D_];
__device__ uint32_t g_Qh[N_*D_];    // [B,H,S,DK] tf32
__device__ uint32_t g_Kh[N_*D_];
__device__ uint32_t g_Vh[N_*D_];
__device__ uint32_t g_ctx[N_*D_];   // [B,S,D] tf32

// ============================ helpers ======================================
__device__ __forceinline__ uint32_t f2tf32(float x) {
    uint32_t r;
    asm("cvt.rna.tf32.f32 %0, %1;" : "=r"(r) : "f"(x));
    return r;
}
__device__ __forceinline__ uint32_t smem_u32(const void* p) {
    uint32_t a;
    asm("{ .reg .u64 t; cvta.to.shared.u64 t, %1; cvt.u32.u64 %0, t; }"
        : "=r"(a) : "l"(p));
    return a;
}
__device__ __forceinline__ void cp16(uint32_t sdst, const void* gsrc) {
    asm volatile("cp.async.cg.shared.global [%0], [%1], 16;"
                 :: "r"(sdst), "l"(gsrc) : "memory");
}
#define CP_COMMIT() asm volatile("cp.async.commit_group;" ::: "memory")
#define CP_WAIT(n)  asm volatile("cp.async.wait_group %0;" :: "n"(n) : "memory")

__device__ __forceinline__ void mma_tf32(float c[4],
                                         uint32_t a0, uint32_t a1, uint32_t a2, uint32_t a3,
                                         uint32_t b0, uint32_t b1) {
    asm volatile(
        "mma.sync.aligned.m16n8k8.row.col.f32.tf32.tf32.f32 "
        "{%0,%1,%2,%3}, {%4,%5,%6,%7}, {%8,%9}, {%0,%1,%2,%3};"
        : "+f"(c[0]), "+f"(c[1]), "+f"(c[2]), "+f"(c[3])
        : "r"(a0), "r"(a1), "r"(a2), "r"(a3), "r"(b0), "r"(b1));
}

// ===========================================================================
// fp32 -> tf32 conversion, all 7 tensors in one launch.
// ===========================================================================
__global__ __launch_bounds__(256) void cvt_all_kernel(
    const float* __restrict__ q, const float* __restrict__ k, const float* __restrict__ v,
    const float* __restrict__ wq, const float* __restrict__ wk,
    const float* __restrict__ wv, const float* __restrict__ wo)
{
    const int y = blockIdx.y;
    const float* src;
    uint32_t* dst;
    switch (y) {
        case 0: src = q;  dst = g_qt;  break;
        case 1: src = k;  dst = g_kt;  break;
        case 2: src = v;  dst = g_vt;  break;
        case 3: src = wq; dst = g_wqt; break;
        case 4: src = wk; dst = g_wkt; break;
        case 5: src = wv; dst = g_wvt; break;
        default: src = wo; dst = g_wot; break;
    }
    if (y >= 3 && blockIdx.x >= 1024) return;
    const int i = (blockIdx.x * 256 + threadIdx.x) * 4;
    const float4 vv = *(const float4*)&src[i];
    uint4 t;
    t.x = f2tf32(vv.x); t.y = f2tf32(vv.y); t.z = f2tf32(vv.z); t.w = f2tf32(vv.w);
    *(uint4*)&dst[i] = t;
}

// ===========================================================================
// tf32 GEMM v3: 128 threads, 4 warps (2m x 2n), warp tile 64x64 (mt=4, nt=8).
// LDS-per-MMA drops 1.5 -> 1.0 (smem crossbar is the measured bottleneck).
// cp.async 3-stage, CTA tile 128x128, K-chunk 32. No reg cap (2 CTAs fit RF).
// QKV=true: blockIdx.z in {0,1,2} selects (q,k,v) triple, SPLIT layout out.
// ===========================================================================
#define AS_STRIDE 36
#define BS_STRIDE 136
#define AST_FLOATS (128 * AS_STRIDE)
#define BST_FLOATS (32 * BS_STRIDE)
#define STG_FLOATS (AST_FLOATS + BST_FLOATS)
#define GEMM_SMEM (3 * STG_FLOATS * 4)   // 107520 B

template<bool QKV>
__global__ __launch_bounds__(128, 2)
void gemm_cp_kernel(const uint32_t* __restrict__ A0, const uint32_t* __restrict__ B0,
                    const float* __restrict__ bias0, void* __restrict__ Y0)
{
    extern __shared__ uint32_t smu[];
    const uint32_t smem_base = smem_u32(smu);

    const uint32_t* A_;
    const uint32_t* Bm;
    const float* bias;
    void* Yv;
    if (QKV) {
        const int z = blockIdx.z;
        A_   = (z == 0) ? g_qt  : (z == 1) ? g_kt  : g_vt;
        Bm   = (z == 0) ? g_wqt : (z == 1) ? g_wkt : g_wvt;
        bias = (z == 0) ? bias0 : (z == 1) ? (const float*)B0 : (const float*)Y0;
        Yv   = (z == 0) ? (void*)g_Qh : (z == 1) ? (void*)g_Kh : (void*)g_Vh;
    } else {
        A_ = A0; Bm = B0; bias = bias0; Yv = Y0;
    }

    const int tid  = threadIdx.x;
    const int wid  = tid >> 5, lane = tid & 31;
    const int g    = lane >> 2, t4 = lane & 3;
    const int wm   = wid >> 1, wn = wid & 1;      // 2 x 2 warp grid, 64x64 tiles
    const int rowBase = blockIdx.y * 128;
    const int colBase = blockIdx.x * 128;

    auto issue = [&](int ch, int stg) {
        const uint32_t abase = smem_base + (uint32_t)stg * (STG_FLOATS * 4);
        const uint32_t bbase = abase + AST_FLOATS * 4;
        #pragma unroll
        for (int j = 0; j < 8; j++) {
            const int slot = tid + 128 * j;        // 0..1023 float4 slots
            const int row = slot >> 3, f4 = slot & 7;
            cp16(abase + (row * AS_STRIDE + f4 * 4) * 4,
                 A_ + (size_t)(rowBase + row) * D_ + ch * 32 + f4 * 4);
            const int kr = slot >> 5, nq = slot & 31;
            cp16(bbase + (kr * BS_STRIDE + nq * 4) * 4,
                 Bm + (size_t)(ch * 32 + kr) * D_ + colBase + nq * 4);
        }
        CP_COMMIT();
    };

    float acc[4][8][4];
    #pragma unroll
    for (int mt = 0; mt < 4; mt++)
        #pragma unroll
        for (int nt = 0; nt < 8; nt++)
            #pragma unroll
            for (int r = 0; r < 4; r++) acc[mt][nt][r] = 0.f;

    issue(0, 0);
    issue(1, 1);

    const int am0 = wm * 64;
    const int bn0 = wn * 64;

    for (int ch = 0; ch < 32; ch++) {
        CP_WAIT(1);
        __syncthreads();   // stage data visible; all warps done with stage ch%3 prev lap

        if (ch + 2 < 32) issue(ch + 2, (ch + 2) % 3);

        const uint32_t* A  = smu + (ch % 3) * STG_FLOATS;
        const uint32_t* Bv = A + AST_FLOATS;

        #pragma unroll
        for (int ks = 0; ks < 4; ks++) {
            const int k0 = ks * 8;
            uint32_t a[4][4];
            #pragma unroll
            for (int mt = 0; mt < 4; mt++) {
                const int m0 = am0 + mt * 16;
                a[mt][0] = A[(m0 + g    ) * AS_STRIDE + k0 + t4    ];
                a[mt][1] = A[(m0 + g + 8) * AS_STRIDE + k0 + t4    ];
                a[mt][2] = A[(m0 + g    ) * AS_STRIDE + k0 + t4 + 4];
                a[mt][3] = A[(m0 + g + 8) * AS_STRIDE + k0 + t4 + 4];
            }
            #pragma unroll
            for (int nt = 0; nt < 8; nt++) {
                const int n0 = bn0 + nt * 8;
                const uint32_t b0 = Bv[(k0 + t4    ) * BS_STRIDE + n0 + g];
                const uint32_t b1 = Bv[(k0 + t4 + 4) * BS_STRIDE + n0 + g];
                #pragma unroll
                for (int mt = 0; mt < 4; mt++)
                    mma_tf32(acc[mt][nt], a[mt][0], a[mt][1], a[mt][2], a[mt][3], b0, b1);
            }
        }
    }

    #pragma unroll
    for (int mt = 0; mt < 4; mt++) {
        const int r0 = rowBase + am0 + mt * 16 + g;
        #pragma unroll
        for (int nt = 0; nt < 8; nt++) {
            const int cb = colBase + bn0 + nt * 8 + t4 * 2;
            const float2 bb = *(const float2*)&bias[cb];
            float2 v0, v1;
            v0.x = acc[mt][nt][0] + bb.x; v0.y = acc[mt][nt][1] + bb.y;
            v1.x = acc[mt][nt][2] + bb.x; v1.y = acc[mt][nt][3] + bb.y;
            if (QKV) {
                uint32_t* Y = (uint32_t*)Yv;
                const int h = cb >> 6, dk = cb & (DK_-1);
                const int b0i = r0 >> 11, s0 = r0 & (S_-1);
                uint2 u0; u0.x = f2tf32(v0.x); u0.y = f2tf32(v0.y);
                *(uint2*)&Y[(((b0i*H_ + h)*S_) + s0)*DK_ + dk] = u0;
                const int r1 = r0 + 8;
                const int b1i = r1 >> 11, s1 = r1 & (S_-1);
                uint2 u1; u1.x = f2tf32(v1.x); u1.y = f2tf32(v1.y);
                *(uint2*)&Y[(((b1i*H_ + h)*S_) + s1)*DK_ + dk] = u1;
            } else {
                float* Y = (float*)Yv;
                *(float2*)&Y[(size_t)r0 * D_ + cb] = v0;
                *(float2*)&Y[(size_t)(r0 + 8) * D_ + cb] = v1;
            }
        }
    }
}

// ===========================================================================
// Causal flash attention v3b (unchanged from round 16): tf32 mma.sync,
// 2 CTAs/SM, Q in smem plane, 2 barriers/iter phase-split cp.async pipeline.
// smem: Qs[128][68] + Ks[64][68] + Vs[64][68] + Ps[128][68] = 104448 B.
// ===========================================================================
#define ATT_STRIDE 68
#define KV_FLOATS (64 * ATT_STRIDE)
#define Q_FLOATS  (128 * ATT_STRIDE)
#define ATT_SMEM ((2 * Q_FLOATS + 2 * KV_FLOATS) * 4)   // 104448

__global__ __launch_bounds__(256, 2)
void attn_mma_kernel(uint32_t* __restrict__ ctx)
{
    extern __shared__ uint32_t smw[];
    uint32_t* Qs = smw;                       // [128][68]
    uint32_t* Ks = smw + Q_FLOATS;            // [64][68]
    uint32_t* Vs = Ks + KV_FLOATS;            // [64][68]
    uint32_t* Ps = Vs + KV_FLOATS;            // [128][68]
    const uint32_t smem_base = smem_u32(smw);
    const uint32_t koff = smem_base + Q_FLOATS * 4;
    const uint32_t voff = koff + KV_FLOATS * 4;

    const int tid  = threadIdx.x;
    const int wid  = tid >> 5, lane = tid & 31;
    const int g    = lane >> 2, t4 = lane & 3;
    const int qt   = (int)gridDim.x - 1 - (int)blockIdx.x;   // heavy tiles first
    const int bh   = blockIdx.y;
    const int m0   = wid * 16;

    const uint32_t* Qg = g_Qh + (size_t)bh * (S_*DK_) + qt * 128 * DK_;
    const uint32_t* Kg = g_Kh + (size_t)bh * (S_*DK_);
    const uint32_t* Vg = g_Vh + (size_t)bh * (S_*DK_);

    // ---- prologue: one group = Q plane + K tile 0 ----
    #pragma unroll
    for (int j = 0; j < 8; j++) {
        const int slot = tid + 256 * j;            // 0..2047
        const int row = slot >> 4, cq = (slot & 15) * 4;
        cp16(smem_base + (row * ATT_STRIDE + cq) * 4,
             Qg + (size_t)row * DK_ + cq);
    }
    #pragma unroll
    for (int j = 0; j < 4; j++) {
        const int slot = tid + 256 * j;
        const int row = slot >> 4, cq = (slot & 15) * 4;
        cp16(koff + (row * ATT_STRIDE + cq) * 4,
             Kg + (size_t)row * DK_ + cq);
    }
    CP_COMMIT();

    float m[2] = { -1e30f, -1e30f };
    float l[2] = { 0.f, 0.f };
    float o[8][4];
    #pragma unroll
    for (int nt = 0; nt < 8; nt++)
        #pragma unroll
        for (int r = 0; r < 4; r++) o[nt][r] = 0.f;

    const int nk = 2 * qt + 2;
    const int rowg0 = qt * 128 + m0 + g;

    for (int kt = 0; kt < nk; kt++) {
        const bool has_next = (kt + 1 < nk);

        // ---- top: K(kt) (and Q on iter 0) complete; nothing else in flight ----
        CP_WAIT(0);
        __syncthreads();   // K visible; prev iter's Vs/Ps reads done

        // ---- issue V(kt): lands during QK + softmax ----
        #pragma unroll
        for (int j = 0; j < 4; j++) {
            const int slot = tid + 256 * j;
            const int row = slot >> 4, cq = (slot & 15) * 4;
            cp16(voff + (row * ATT_STRIDE + cq) * 4,
                 Vg + (size_t)(kt * 64 + row) * DK_ + cq);
        }
        CP_COMMIT();

        // ---- S = Q K^T ----
        float sc[8][4];
        #pragma unroll
        for (int nt = 0; nt < 8; nt++)
            #pragma unroll
            for (int r = 0; r < 4; r++) sc[nt][r] = 0.f;

        #pragma unroll
        for (int ks = 0; ks < 8; ks++) {
            const int k0 = ks * 8;
            const uint32_t a0 = Qs[(m0 + g    ) * ATT_STRIDE + k0 + t4    ];
            const uint32_t a1 = Qs[(m0 + g + 8) * ATT_STRIDE + k0 + t4    ];
            const uint32_t a2 = Qs[(m0 + g    ) * ATT_STRIDE + k0 + t4 + 4];
            const uint32_t a3 = Qs[(m0 + g + 8) * ATT_STRIDE + k0 + t4 + 4];
            #pragma unroll
            for (int nt = 0; nt < 8; nt++) {
                const uint32_t b0 = Ks[(nt*8 + g) * ATT_STRIDE + k0 + t4    ];
                const uint32_t b1 = Ks[(nt*8 + g) * ATT_STRIDE + k0 + t4 + 4];
                mma_tf32(sc[nt], a0, a1, a2, a3, b0, b1);
            }
        }

        // ---- scale + causal mask ----
        const bool need_mask = (kt >= 2 * qt);
        const int colBase = kt * 64;
        #pragma unroll
        for (int nt = 0; nt < 8; nt++) {
            #pragma unroll
            for (int r = 0; r < 4; r++) sc[nt][r] *= 0.125f;
            if (need_mask) {
                const int c0 = colBase + nt*8 + 2*t4;
                if (c0     > rowg0    ) sc[nt][0] = -1e30f;
                if (c0 + 1 > rowg0    ) sc[nt][1] = -1e30f;
                if (c0     > rowg0 + 8) sc[nt][2] = -1e30f;
                if (c0 + 1 > rowg0 + 8) sc[nt][3] = -1e30f;
            }
        }

        // ---- online softmax ----
        #pragma unroll
        for (int r = 0; r < 2; r++) {
            float rm = -1e30f;
            #pragma unroll
            for (int nt = 0; nt < 8; nt++)
                rm = fmaxf(rm, fmaxf(sc[nt][2*r], sc[nt][2*r+1]));
            rm = fmaxf(rm, __shfl_xor_sync(0xffffffffu, rm, 1));
            rm = fmaxf(rm, __shfl_xor_sync(0xffffffffu, rm, 2));
            const float mn = fmaxf(m[r], rm);
            const float alpha = __expf(m[r] - mn);
            m[r] = mn;
            float rs = 0.f;
            #pragma unroll
            for (int nt = 0; nt < 8; nt++) {
                const float p0 = __expf(sc[nt][2*r  ] - mn);
                const float p1 = __expf(sc[nt][2*r+1] - mn);
                sc[nt][2*r] = p0; sc[nt][2*r+1] = p1;
                rs += p0 + p1;
            }
            rs += __shfl_xor_sync(0xffffffffu, rs, 1);
            rs += __shfl_xor_sync(0xffffffffu, rs, 2);
            l[r] = l[r] * alpha + rs;
            #pragma unroll
            for (int nt = 0; nt < 8; nt++) {
                o[nt][2*r] *= alpha; o[nt][2*r+1] *= alpha;
            }
        }

        // ---- P -> Ps (warp-private rows) ----
        __syncwarp();
        #pragma unroll
        for (int nt = 0; nt < 8; nt++) {
            uint2 w0, w1;
            w0.x = f2tf32(sc[nt][0]); w0.y = f2tf32(sc[nt][1]);
            w1.x = f2tf32(sc[nt][2]); w1.y = f2tf32(sc[nt][3]);
            *(uint2*)&Ps[(m0 + g    ) * ATT_STRIDE + nt*8 + 2*t4] = w0;
            *(uint2*)&Ps[(m0 + g + 8) * ATT_STRIDE + nt*8 + 2*t4] = w1;
        }
        __syncwarp();

        // ---- pre-PV: V(kt) complete; barrier also closes all QK reads ----
        CP_WAIT(0);
        __syncthreads();

        // ---- issue K(kt+1): overlaps PV; completes by next top WAIT(0) ----
        if (has_next) {
            #pragma unroll
            for (int j = 0; j < 4; j++) {
                const int slot = tid + 256 * j;
                const int row = slot >> 4, cq = (slot & 15) * 4;
                cp16(koff + (row * ATT_STRIDE + cq) * 4,
                     Kg + (size_t)((kt + 1) * 64 + row) * DK_ + cq);
            }
            CP_COMMIT();
        }

        // ---- O += P V ----
        #pragma unroll
        for (int ks = 0; ks < 8; ks++) {
            const int k0 = ks * 8;
            const uint32_t a0 = Ps[(m0 + g    ) * ATT_STRIDE + k0 + t4    ];
            const uint32_t a1 = Ps[(m0 + g + 8) * ATT_STRIDE + k0 + t4    ];
            const uint32_t a2 = Ps[(m0 + g    ) * ATT_STRIDE + k0 + t4 + 4];
            const uint32_t a3 = Ps[(m0 + g + 8) * ATT_STRIDE + k0 + t4 + 4];
            #pragma unroll
            for (int nt = 0; nt < 8; nt++) {
                const uint32_t b0 = Vs[(k0 + t4    ) * ATT_STRIDE + nt*8 + g];
                const uint32_t b1 = Vs[(k0 + t4 + 4) * ATT_STRIDE + nt*8 + g];
                mma_tf32(o[nt], a0, a1, a2, a3, b0, b1);
            }
        }
        // next iteration's top barrier protects Vs/Ps before refill
    }

    // ---- epilogue: normalize, store ctx tf32 bits [B,S,D] ----
    const int b = bh >> 4, h = bh & 15;
    #pragma unroll
    for (int r = 0; r < 2; r++) {
        const float inv = 1.0f / l[r];
        const int srow = qt*128 + m0 + g + (r ? 8 : 0);
        uint32_t* dst = &ctx[((size_t)b * S_ + srow) * D_ + h * DK_];
        #pragma unroll
        for (int nt = 0; nt < 8; nt++) {
            uint2 v;
            v.x = f2tf32(o[nt][2*r  ] * inv);
            v.y = f2tf32(o[nt][2*r+1] * inv);
            *(uint2*)&dst[nt*8 + 2*t4] = v;
        }
    }
}

// ---------------------------------------------------------------------------
extern "C" void kernel_launch(void* const* d_in, const int* in_sizes, int n_in,
                              void* d_out, int out_size)
{
    const float* q   = (const float*)d_in[0];
    const float* k   = (const float*)d_in[1];
    const float* v   = (const float*)d_in[2];
    // d_in[3] = mask (causal, applied analytically)
    const float* w_q = (const float*)d_in[4];
    const float* b_q = (const float*)d_in[5];
    const float* w_k = (const float*)d_in[6];
    const float* b_k = (const float*)d_in[7];
    const float* w_v = (const float*)d_in[8];
    const float* b_v = (const float*)d_in[9];
    const float* w_o = (const float*)d_in[10];
    const float* b_o = (const float*)d_in[11];
    float* out = (float*)d_out;

    uint32_t *wot, *ctx;
    cudaGetSymbolAddress((void**)&wot, g_wot);
    cudaGetSymbolAddress((void**)&ctx, g_ctx);

    cudaFuncSetAttribute(gemm_cp_kernel<true>,
                         cudaFuncAttributeMaxDynamicSharedMemorySize, GEMM_SMEM);
    cudaFuncSetAttribute(gemm_cp_kernel<false>,
                         cudaFuncAttributeMaxDynamicSharedMemorySize, GEMM_SMEM);
    cudaFuncSetAttribute(attn_mma_kernel,
                         cudaFuncAttributeMaxDynamicSharedMemorySize, ATT_SMEM);

    cvt_all_kernel<<<dim3(N_*D_/1024, 7), 256>>>(q, k, v, w_q, w_k, w_v, w_o);

    // merged QKV projections: z selects stream; biases smuggled via B0/bias0/Y0
    gemm_cp_kernel<true ><<<dim3(D_/128, N_/128, 3), 128, GEMM_SMEM>>>(
        nullptr, (const uint32_t*)b_k, b_q, (void*)b_v);

    attn_mma_kernel<<<dim3(S_/128, B_*H_), 256, ATT_SMEM>>>(ctx);

    gemm_cp_kernel<false><<<dim3(D_/128, N_/128), 128, GEMM_SMEM>>>(ctx, wot, b_o, out);
}